// round 6
// baseline (speedup 1.0000x reference)
#include <cuda_runtime.h>

// DynamicMaskHead: per-instance 3-layer 1x1-conv MLP (10->8->8->1) over 27200 pixels.
// f32x2 FMA, transposed duplicated weights in shared, 8 pixels/thread
// (two 4-pixel quads processed sequentially to bound register pressure).

#define H_      136
#define W_      200
#define HW_     27200
#define CH_     8
#define INCH_   8
#define NINST_  128
#define NP_     169
#define STRIDE_ 8

#define BLK    256
#define NQ     (HW_ / 4)                 // 6800 float4 quads
#define QPBLK  (BLK * 2)                 // 512 quads per block
#define GRIDX  ((NQ + QPBLK - 1) / QPBLK)  // 14

typedef unsigned long long u64;

__device__ __forceinline__ u64 pack2(float lo, float hi) {
    u64 r; asm("mov.b64 %0, {%1, %2};" : "=l"(r) : "f"(lo), "f"(hi)); return r;
}
__device__ __forceinline__ void unpack2(u64 v, float& lo, float& hi) {
    asm("mov.b64 {%0, %1}, %2;" : "=f"(lo), "=f"(hi) : "l"(v));
}
__device__ __forceinline__ u64 ffma2(u64 a, u64 b, u64 c) {
    u64 d; asm("fma.rn.f32x2 %0, %1, %2, %3;" : "=l"(d) : "l"(a), "l"(b), "l"(c)); return d;
}
__device__ __forceinline__ u64 relu2(u64 v) {
    float lo, hi; unpack2(v, lo, hi);
    return pack2(fmaxf(lo, 0.0f), fmaxf(hi, 0.0f));
}

// gmem params: w0 [0,80) (8x10) | w1 [80,144) (8x8) | w2 [144,152)
//              b0 [152,160) | b1 [160,168) | b2 [168]
struct __align__(16) SmemParams {
    u64 sw0t[80];   // sw0t[i*8+o] = w0[o][i]  (input-major, duplicated lanes)
    u64 sw1t[64];   // sw1t[i*8+o] = w1[o][i]
    u64 sw2[8];
    u64 sb0[8];
    u64 sb1[8];
    u64 sb2[2];
};

__global__ __launch_bounds__(BLK, 3)
void dmh_kernel(const float* __restrict__ feats,   // (2, 8, HW)
                const float* __restrict__ params,  // (128, 169)
                const float* __restrict__ locs,    // (128, 2)
                const float* __restrict__ soi,     // (5,)
                const int*   __restrict__ im_inds, // (128,)
                const int*   __restrict__ fpn,     // (128,)
                float*       __restrict__ out)     // (128, HW)
{
    __shared__ SmemParams S;
    __shared__ float smeta[3];
    __shared__ int   simg;

    const int inst = blockIdx.y;
    const int tid  = threadIdx.x;

    if (tid < NP_) {
        const float w = params[inst * NP_ + tid];
        const u64 d = pack2(w, w);
        if (tid < 80) {
            const int o = tid / 10, i = tid - o * 10;
            S.sw0t[i * 8 + o] = d;
        } else if (tid < 144) {
            const int k = tid - 80;
            S.sw1t[(k & 7) * 8 + (k >> 3)] = d;
        } else if (tid < 152) {
            S.sw2[tid - 144] = d;
        } else if (tid < 160) {
            S.sb0[tid - 152] = d;
        } else if (tid < 168) {
            S.sb1[tid - 160] = d;
        } else {
            S.sb2[0] = d;
        }
    }
    if (tid == 0) {
        smeta[0] = locs[2 * inst + 0];
        smeta[1] = locs[2 * inst + 1];
        smeta[2] = 1.0f / soi[fpn[inst]];
        simg     = im_inds[inst];
    }
    __syncthreads();

    const float locx = smeta[0];
    const float locy = smeta[1];
    const float inv  = smeta[2];
    const float* __restrict__ fbase = feats + (size_t)simg * (INCH_ * HW_);
    float* __restrict__ obase = out + (size_t)inst * HW_;

    const int qbase = blockIdx.x * QPBLK + tid;

    #pragma unroll
    for (int half = 0; half < 2; half++) {
        const int q    = qbase + half * BLK;
        const bool live = (q < NQ);
        const int qc   = live ? q : 0;
        const int p0   = qc * 4;                 // 4 consecutive pixels, one row

        const int row  = qc / 50;
        const int col0 = (qc - row * 50) * 4;
        const float fy  = (float)(row * STRIDE_ + STRIDE_ / 2);
        const float fx0 = (float)(col0 * STRIDE_ + STRIDE_ / 2);

        // ---- layer 0 (fused over both pixel-pair banks): 10 -> 8 ----
        u64 h[2][CH_];
        {
            const ulonglong2* b = reinterpret_cast<const ulonglong2*>(S.sb0);
            #pragma unroll
            for (int oq = 0; oq < 4; oq++) {
                const ulonglong2 bb = b[oq];
                h[0][2*oq]   = bb.x;  h[1][2*oq]   = bb.x;
                h[0][2*oq+1] = bb.y;  h[1][2*oq+1] = bb.y;
            }
        }

        #define ACC2(WROW)                                                        \
            {                                                                     \
                const ulonglong2* wr = reinterpret_cast<const ulonglong2*>(WROW); \
                _Pragma("unroll")                                                 \
                for (int oq = 0; oq < 4; oq++) {                                  \
                    const ulonglong2 w = wr[oq];                                  \
                    h[0][2*oq]   = ffma2(w.x, x0, h[0][2*oq]);                    \
                    h[1][2*oq]   = ffma2(w.x, x1, h[1][2*oq]);                    \
                    h[0][2*oq+1] = ffma2(w.y, x0, h[0][2*oq+1]);                  \
                    h[1][2*oq+1] = ffma2(w.y, x1, h[1][2*oq+1]);                  \
                }                                                                 \
            }

        {   // rel-x
            const u64 x0 = pack2((locx - fx0) * inv,           (locx - (fx0 +  8.0f)) * inv);
            const u64 x1 = pack2((locx - (fx0 + 16.0f)) * inv, (locx - (fx0 + 24.0f)) * inv);
            ACC2(&S.sw0t[0])
        }
        {   // rel-y (uniform across the 4 pixels)
            const float ry = (locy - fy) * inv;
            const u64 x0 = pack2(ry, ry);
            const u64 x1 = x0;
            ACC2(&S.sw0t[8])
        }
        #pragma unroll
        for (int c = 0; c < INCH_; c++) {   // feature channels: LDG.128
            const ulonglong2 f =
                *reinterpret_cast<const ulonglong2*>(fbase + (size_t)c * HW_ + p0);
            const u64 x0 = f.x;
            const u64 x1 = f.y;
            ACC2(&S.sw0t[(2 + c) * 8])
        }
        #undef ACC2

        #pragma unroll
        for (int o = 0; o < CH_; o++) {
            h[0][o] = relu2(h[0][o]);
            h[1][o] = relu2(h[1][o]);
        }

        // ---- layer 1: 8 -> 8 (both banks fused) ----
        u64 a1[2][CH_];
        {
            const ulonglong2* b = reinterpret_cast<const ulonglong2*>(S.sb1);
            #pragma unroll
            for (int oq = 0; oq < 4; oq++) {
                const ulonglong2 bb = b[oq];
                a1[0][2*oq]   = bb.x;  a1[1][2*oq]   = bb.x;
                a1[0][2*oq+1] = bb.y;  a1[1][2*oq+1] = bb.y;
            }
        }
        #pragma unroll
        for (int i = 0; i < CH_; i++) {
            const u64 x0 = h[0][i];
            const u64 x1 = h[1][i];
            const ulonglong2* wr = reinterpret_cast<const ulonglong2*>(&S.sw1t[i * 8]);
            #pragma unroll
            for (int oq = 0; oq < 4; oq++) {
                const ulonglong2 w = wr[oq];
                a1[0][2*oq]   = ffma2(w.x, x0, a1[0][2*oq]);
                a1[1][2*oq]   = ffma2(w.x, x1, a1[1][2*oq]);
                a1[0][2*oq+1] = ffma2(w.y, x0, a1[0][2*oq+1]);
                a1[1][2*oq+1] = ffma2(w.y, x1, a1[1][2*oq+1]);
            }
        }

        // ---- layer 2: 8 -> 1 (relu folded in) ----
        u64 r0 = S.sb2[0];
        u64 r1 = r0;
        {
            const ulonglong2* wr = reinterpret_cast<const ulonglong2*>(S.sw2);
            #pragma unroll
            for (int iq = 0; iq < 4; iq++) {
                const ulonglong2 w = wr[iq];
                r0 = ffma2(w.x, relu2(a1[0][2*iq]),   r0);
                r1 = ffma2(w.x, relu2(a1[1][2*iq]),   r1);
                r0 = ffma2(w.y, relu2(a1[0][2*iq+1]), r0);
                r1 = ffma2(w.y, relu2(a1[1][2*iq+1]), r1);
            }
        }

        if (live) {
            ulonglong2 o2;
            o2.x = r0;
            o2.y = r1;
            *reinterpret_cast<ulonglong2*>(obase + p0) = o2;
        }
    }
}

extern "C" void kernel_launch(void* const* d_in, const int* in_sizes, int n_in,
                              void* d_out, int out_size)
{
    const float* feats   = (const float*)d_in[0];
    const float* params  = (const float*)d_in[1];
    const float* locs    = (const float*)d_in[2];
    const float* soi     = (const float*)d_in[3];
    const int*   im_inds = (const int*)  d_in[4];
    const int*   fpn     = (const int*)  d_in[5];
    float*       out     = (float*)      d_out;

    dim3 grid(GRIDX, NINST_);
    dmh_kernel<<<grid, BLK>>>(feats, params, locs, soi, im_inds, fpn, out);
}

// round 7
// speedup vs baseline: 4.8690x; 4.8690x over previous
#include <cuda_runtime.h>

// DynamicMaskHead: per-instance 3-layer 1x1-conv MLP (10->8->8->1) over 27200 pixels.
// f32x2 FMA, transposed duplicated weights in shared, 2 pixels/thread (single
// f32x2 bank) to minimize register pressure -> 3 blocks x 512 threads per SM.

#define H_      136
#define W_      200
#define HW_     27200
#define CH_     8
#define INCH_   8
#define NINST_  128
#define NP_     169
#define STRIDE_ 8

#define BLK    512
#define NG2    (HW_ / 2)                  // 13600 pixel-pairs
#define GRIDX  ((NG2 + BLK - 1) / BLK)    // 27

typedef unsigned long long u64;

__device__ __forceinline__ u64 pack2(float lo, float hi) {
    u64 r; asm("mov.b64 %0, {%1, %2};" : "=l"(r) : "f"(lo), "f"(hi)); return r;
}
__device__ __forceinline__ u64 ffma2(u64 a, u64 b, u64 c) {
    u64 d; asm("fma.rn.f32x2 %0, %1, %2, %3;" : "=l"(d) : "l"(a), "l"(b), "l"(c)); return d;
}
__device__ __forceinline__ u64 relu2(u64 v) {
    float lo, hi;
    asm("mov.b64 {%0, %1}, %2;" : "=f"(lo), "=f"(hi) : "l"(v));
    return pack2(fmaxf(lo, 0.0f), fmaxf(hi, 0.0f));
}

// gmem params: w0 [0,80) (8x10) | w1 [80,144) (8x8) | w2 [144,152)
//              b0 [152,160) | b1 [160,168) | b2 [168]
struct __align__(16) SmemParams {
    u64 sw0t[80];   // sw0t[i*8+o] = w0[o][i]  (input-major, duplicated lanes)
    u64 sw1t[64];   // sw1t[i*8+o] = w1[o][i]
    u64 sw2[8];
    u64 sb0[8];
    u64 sb1[8];
    u64 sb2[2];
};

__global__ __launch_bounds__(BLK, 3)
void dmh_kernel(const float* __restrict__ feats,   // (2, 8, HW)
                const float* __restrict__ params,  // (128, 169)
                const float* __restrict__ locs,    // (128, 2)
                const float* __restrict__ soi,     // (5,)
                const int*   __restrict__ im_inds, // (128,)
                const int*   __restrict__ fpn,     // (128,)
                float*       __restrict__ out)     // (128, HW)
{
    __shared__ SmemParams S;
    __shared__ float smeta[3];
    __shared__ int   simg;

    const int inst = blockIdx.y;
    const int tid  = threadIdx.x;

    if (tid < NP_) {
        const float w = params[inst * NP_ + tid];
        const u64 d = pack2(w, w);
        if (tid < 80) {
            const int o = tid / 10, i = tid - o * 10;
            S.sw0t[i * 8 + o] = d;
        } else if (tid < 144) {
            const int k = tid - 80;
            S.sw1t[(k & 7) * 8 + (k >> 3)] = d;
        } else if (tid < 152) {
            S.sw2[tid - 144] = d;
        } else if (tid < 160) {
            S.sb0[tid - 152] = d;
        } else if (tid < 168) {
            S.sb1[tid - 160] = d;
        } else {
            S.sb2[0] = d;
        }
    }
    if (tid == 0) {
        smeta[0] = locs[2 * inst + 0];
        smeta[1] = locs[2 * inst + 1];
        smeta[2] = 1.0f / soi[fpn[inst]];
        simg     = im_inds[inst];
    }
    __syncthreads();

    const int g    = blockIdx.x * BLK + tid;   // pixel-pair index
    const bool live = (g < NG2);
    const int gc   = live ? g : 0;
    const int p0   = gc * 2;                   // 2 consecutive pixels, same row (W even)

    // ---- layer 0: 10 -> 8 ----
    u64 h[CH_];
    {
        const ulonglong2* b = reinterpret_cast<const ulonglong2*>(S.sb0);
        #pragma unroll
        for (int oq = 0; oq < 4; oq++) {
            const ulonglong2 bb = b[oq];
            h[2*oq]   = bb.x;
            h[2*oq+1] = bb.y;
        }
    }

    #define ACC1(WROW, X)                                                     \
        {                                                                     \
            const ulonglong2* wr = reinterpret_cast<const ulonglong2*>(WROW); \
            _Pragma("unroll")                                                 \
            for (int oq = 0; oq < 4; oq++) {                                  \
                const ulonglong2 w = wr[oq];                                  \
                h[2*oq]   = ffma2(w.x, (X), h[2*oq]);                         \
                h[2*oq+1] = ffma2(w.y, (X), h[2*oq+1]);                       \
            }                                                                 \
        }

    {   // rel-x: pixels p0, p0+1
        const int row  = gc / 100;             // 100 pairs per row
        const int col0 = (gc - row * 100) * 2;
        const float inv  = smeta[2];
        const float fx0  = (float)(col0 * STRIDE_ + STRIDE_ / 2);
        const float locx = smeta[0];
        const u64 x = pack2((locx - fx0) * inv, (locx - (fx0 + 8.0f)) * inv);
        ACC1(&S.sw0t[0], x)
        // rel-y (uniform across the pair)
        const float ry = (smeta[1] - (float)(row * STRIDE_ + STRIDE_ / 2)) * inv;
        const u64 y = pack2(ry, ry);
        ACC1(&S.sw0t[8], y)
    }
    {
        const float* __restrict__ fb = feats + (size_t)simg * (INCH_ * HW_) + p0;
        #pragma unroll
        for (int c = 0; c < INCH_; c++) {      // feature channels: LDG.64 each
            const u64 x = *reinterpret_cast<const u64*>(fb + (size_t)c * HW_);
            ACC1(&S.sw0t[(2 + c) * 8], x)
        }
    }
    #undef ACC1

    #pragma unroll
    for (int o = 0; o < CH_; o++) h[o] = relu2(h[o]);

    // ---- layer 1: 8 -> 8 ----
    u64 a1[CH_];
    {
        const ulonglong2* b = reinterpret_cast<const ulonglong2*>(S.sb1);
        #pragma unroll
        for (int oq = 0; oq < 4; oq++) {
            const ulonglong2 bb = b[oq];
            a1[2*oq]   = bb.x;
            a1[2*oq+1] = bb.y;
        }
    }
    #pragma unroll
    for (int i = 0; i < CH_; i++) {
        const u64 x = h[i];
        const ulonglong2* wr = reinterpret_cast<const ulonglong2*>(&S.sw1t[i * 8]);
        #pragma unroll
        for (int oq = 0; oq < 4; oq++) {
            const ulonglong2 w = wr[oq];
            a1[2*oq]   = ffma2(w.x, x, a1[2*oq]);
            a1[2*oq+1] = ffma2(w.y, x, a1[2*oq+1]);
        }
    }

    // ---- layer 2: 8 -> 1 (relu folded) ----
    u64 r = S.sb2[0];
    {
        const ulonglong2* wr = reinterpret_cast<const ulonglong2*>(S.sw2);
        #pragma unroll
        for (int iq = 0; iq < 4; iq++) {
            const ulonglong2 w = wr[iq];
            r = ffma2(w.x, relu2(a1[2*iq]),   r);
            r = ffma2(w.y, relu2(a1[2*iq+1]), r);
        }
    }

    if (live)
        *reinterpret_cast<u64*>(out + (size_t)inst * HW_ + p0) = r;
}

extern "C" void kernel_launch(void* const* d_in, const int* in_sizes, int n_in,
                              void* d_out, int out_size)
{
    const float* feats   = (const float*)d_in[0];
    const float* params  = (const float*)d_in[1];
    const float* locs    = (const float*)d_in[2];
    const float* soi     = (const float*)d_in[3];
    const int*   im_inds = (const int*)  d_in[4];
    const int*   fpn     = (const int*)  d_in[5];
    float*       out     = (float*)      d_out;

    dim3 grid(GRIDX, NINST_);
    dmh_kernel<<<grid, BLK>>>(feats, params, locs, soi, im_inds, fpn, out);
}

// round 8
// speedup vs baseline: 6.7867x; 1.3938x over previous
#include <cuda_runtime.h>

// DynamicMaskHead: per-instance 3-layer 1x1-conv MLP (10->8->8->1) over 27200 pixels.
// f32x2 FMA, transposed duplicated weights in shared, 4 pixels/thread.
// R8: front-batched feature LDGs (MLP=8) overlapped with rel-coord FMA work.

#define H_      136
#define W_      200
#define HW_     27200
#define CH_     8
#define INCH_   8
#define NINST_  128
#define NP_     169
#define STRIDE_ 8

#define BLK   256
#define NQ    (HW_ / 4)                 // 6800 float4 quads
#define GRIDX ((NQ + BLK - 1) / BLK)    // 27

typedef unsigned long long u64;

__device__ __forceinline__ u64 pack2(float lo, float hi) {
    u64 r; asm("mov.b64 %0, {%1, %2};" : "=l"(r) : "f"(lo), "f"(hi)); return r;
}
__device__ __forceinline__ void unpack2(u64 v, float& lo, float& hi) {
    asm("mov.b64 {%0, %1}, %2;" : "=f"(lo), "=f"(hi) : "l"(v));
}
__device__ __forceinline__ u64 ffma2(u64 a, u64 b, u64 c) {
    u64 d; asm("fma.rn.f32x2 %0, %1, %2, %3;" : "=l"(d) : "l"(a), "l"(b), "l"(c)); return d;
}
__device__ __forceinline__ u64 relu2(u64 v) {
    float lo, hi; unpack2(v, lo, hi);
    return pack2(fmaxf(lo, 0.0f), fmaxf(hi, 0.0f));
}

// gmem params: w0 [0,80) (8x10) | w1 [80,144) (8x8) | w2 [144,152)
//              b0 [152,160) | b1 [160,168) | b2 [168]
struct __align__(16) SmemParams {
    u64 sw0t[80];   // sw0t[i*8+o] = w0[o][i]  (input-major, duplicated lanes)
    u64 sw1t[64];   // sw1t[i*8+o] = w1[o][i]
    u64 sw2[8];
    u64 sb0[8];
    u64 sb1[8];
    u64 sb2[2];
};

__global__ __launch_bounds__(BLK, 3)
void dmh_kernel(const float* __restrict__ feats,   // (2, 8, HW)
                const float* __restrict__ params,  // (128, 169)
                const float* __restrict__ locs,    // (128, 2)
                const float* __restrict__ soi,     // (5,)
                const int*   __restrict__ im_inds, // (128,)
                const int*   __restrict__ fpn,     // (128,)
                float*       __restrict__ out)     // (128, HW)
{
    __shared__ SmemParams S;
    __shared__ float smeta[3];
    __shared__ int   simg;

    const int inst = blockIdx.y;
    const int tid  = threadIdx.x;

    if (tid < NP_) {
        const float w = params[inst * NP_ + tid];
        const u64 d = pack2(w, w);
        if (tid < 80) {
            const int o = tid / 10, i = tid - o * 10;
            S.sw0t[i * 8 + o] = d;
        } else if (tid < 144) {
            const int k = tid - 80;
            S.sw1t[(k & 7) * 8 + (k >> 3)] = d;
        } else if (tid < 152) {
            S.sw2[tid - 144] = d;
        } else if (tid < 160) {
            S.sb0[tid - 152] = d;
        } else if (tid < 168) {
            S.sb1[tid - 160] = d;
        } else {
            S.sb2[0] = d;
        }
    }
    if (tid == 0) {
        smeta[0] = locs[2 * inst + 0];
        smeta[1] = locs[2 * inst + 1];
        smeta[2] = 1.0f / soi[fpn[inst]];
        simg     = im_inds[inst];
    }
    __syncthreads();

    const int q    = blockIdx.x * BLK + tid;
    const bool live = (q < NQ);
    const int qc   = live ? q : 0;
    const int p0   = qc * 4;                 // 4 consecutive pixels, one row

    // ---- front-batch all 8 feature-channel loads (independent, MLP=8) ----
    const float* __restrict__ fbase = feats + (size_t)simg * (INCH_ * HW_) + p0;
    ulonglong2 f[INCH_];
    #pragma unroll
    for (int c = 0; c < INCH_; c++)
        f[c] = *reinterpret_cast<const ulonglong2*>(fbase + (size_t)c * HW_);

    // ---- overlap: rel-coord computation + bias init + rel ACCs ----
    const int row  = qc / 50;
    const int col0 = (qc - row * 50) * 4;
    const float fy  = (float)(row * STRIDE_ + STRIDE_ / 2);
    const float fx0 = (float)(col0 * STRIDE_ + STRIDE_ / 2);
    const float locx = smeta[0];
    const float locy = smeta[1];
    const float inv  = smeta[2];

    u64 h[2][CH_];
    {
        const ulonglong2* b = reinterpret_cast<const ulonglong2*>(S.sb0);
        #pragma unroll
        for (int oq = 0; oq < 4; oq++) {
            const ulonglong2 bb = b[oq];
            h[0][2*oq]   = bb.x;  h[1][2*oq]   = bb.x;
            h[0][2*oq+1] = bb.y;  h[1][2*oq+1] = bb.y;
        }
    }

    #define ACC2(WROW)                                                        \
        {                                                                     \
            const ulonglong2* wr = reinterpret_cast<const ulonglong2*>(WROW); \
            _Pragma("unroll")                                                 \
            for (int oq = 0; oq < 4; oq++) {                                  \
                const ulonglong2 w = wr[oq];                                  \
                h[0][2*oq]   = ffma2(w.x, x0, h[0][2*oq]);                    \
                h[1][2*oq]   = ffma2(w.x, x1, h[1][2*oq]);                    \
                h[0][2*oq+1] = ffma2(w.y, x0, h[0][2*oq+1]);                  \
                h[1][2*oq+1] = ffma2(w.y, x1, h[1][2*oq+1]);                  \
            }                                                                 \
        }

    {   // rel-x (runs while LDGs are in flight)
        const u64 x0 = pack2((locx - fx0) * inv,           (locx - (fx0 +  8.0f)) * inv);
        const u64 x1 = pack2((locx - (fx0 + 16.0f)) * inv, (locx - (fx0 + 24.0f)) * inv);
        ACC2(&S.sw0t[0])
    }
    {   // rel-y (uniform across the 4 pixels)
        const float ry = (locy - fy) * inv;
        const u64 x0 = pack2(ry, ry);
        const u64 x1 = x0;
        ACC2(&S.sw0t[8])
    }
    // ---- consume the batched feature loads ----
    #pragma unroll
    for (int c = 0; c < INCH_; c++) {
        const u64 x0 = f[c].x;
        const u64 x1 = f[c].y;
        ACC2(&S.sw0t[(2 + c) * 8])
    }
    #undef ACC2

    #pragma unroll
    for (int o = 0; o < CH_; o++) {
        h[0][o] = relu2(h[0][o]);
        h[1][o] = relu2(h[1][o]);
    }

    // ---- layer 1: 8 -> 8 (both banks fused) ----
    u64 a1[2][CH_];
    {
        const ulonglong2* b = reinterpret_cast<const ulonglong2*>(S.sb1);
        #pragma unroll
        for (int oq = 0; oq < 4; oq++) {
            const ulonglong2 bb = b[oq];
            a1[0][2*oq]   = bb.x;  a1[1][2*oq]   = bb.x;
            a1[0][2*oq+1] = bb.y;  a1[1][2*oq+1] = bb.y;
        }
    }
    #pragma unroll
    for (int i = 0; i < CH_; i++) {
        const u64 x0 = h[0][i];
        const u64 x1 = h[1][i];
        const ulonglong2* wr = reinterpret_cast<const ulonglong2*>(&S.sw1t[i * 8]);
        #pragma unroll
        for (int oq = 0; oq < 4; oq++) {
            const ulonglong2 w = wr[oq];
            a1[0][2*oq]   = ffma2(w.x, x0, a1[0][2*oq]);
            a1[1][2*oq]   = ffma2(w.x, x1, a1[1][2*oq]);
            a1[0][2*oq+1] = ffma2(w.y, x0, a1[0][2*oq+1]);
            a1[1][2*oq+1] = ffma2(w.y, x1, a1[1][2*oq+1]);
        }
    }

    // ---- layer 2: 8 -> 1 (relu folded) ----
    u64 r0 = S.sb2[0];
    u64 r1 = r0;
    {
        const ulonglong2* wr = reinterpret_cast<const ulonglong2*>(S.sw2);
        #pragma unroll
        for (int iq = 0; iq < 4; iq++) {
            const ulonglong2 w = wr[iq];
            r0 = ffma2(w.x, relu2(a1[0][2*iq]),   r0);
            r1 = ffma2(w.x, relu2(a1[1][2*iq]),   r1);
            r0 = ffma2(w.y, relu2(a1[0][2*iq+1]), r0);
            r1 = ffma2(w.y, relu2(a1[1][2*iq+1]), r1);
        }
    }

    if (live) {
        ulonglong2 o2;
        o2.x = r0;
        o2.y = r1;
        *reinterpret_cast<ulonglong2*>(out + (size_t)inst * HW_ + p0) = o2;
    }
}

extern "C" void kernel_launch(void* const* d_in, const int* in_sizes, int n_in,
                              void* d_out, int out_size)
{
    const float* feats   = (const float*)d_in[0];
    const float* params  = (const float*)d_in[1];
    const float* locs    = (const float*)d_in[2];
    const float* soi     = (const float*)d_in[3];
    const int*   im_inds = (const int*)  d_in[4];
    const int*   fpn     = (const int*)  d_in[5];
    float*       out     = (float*)      d_out;

    dim3 grid(GRIDX, NINST_);
    dmh_kernel<<<grid, BLK>>>(feats, params, locs, soi, im_inds, fpn, out);
}